// round 5
// baseline (speedup 1.0000x reference)
#include <cuda_runtime.h>
#include <cuda_fp16.h>
#include <math.h>

#define NN 50000
#define NE 1600000
#define H 128
#define NG 50
#define NGR 128
#define TABN 8192
#define WMAX 9.6f
#define GM 64   // gemm M-tile
#define KC 32   // gemm K-chunk staged in smem

// -------- scratch (device globals: allocation-free) --------
__device__ float  g_h[NN * H];
__device__ float  g_hx[NN * H];
__device__ float  g_agg[NN * H];
__device__ float  g_w[NE];
__device__ float  g_tab[TABN * H];        // Wf(w)*C(w) values (fp32)
__device__ __half g_tabd[TABN * H];       // forward deltas (half)
__device__ float  g_gsum[NGR];
__device__ float  g_gcnt[NGR];
__device__ int    g_cnt[NN];
__device__ int    g_off[NN + 1];
__device__ int    g_cur[NN];
__device__ uint2  g_edges[NE];            // {src, (i0<<16)|half(fr)}

__device__ __forceinline__ float ssp(float x) {
    return fmaxf(x, 0.0f) + log1pf(expf(-fabsf(x))) - 0.69314718055994531f;
}

__device__ __forceinline__ void fma2(unsigned long long& d,
                                     unsigned long long a, unsigned long long b) {
    asm("fma.rn.f32x2 %0, %1, %2, %0;" : "+l"(d) : "l"(a), "l"(b));
}

// -------- edge geometry --------
__global__ void edge_w_kernel(const float* __restrict__ pos,
                              const float* __restrict__ shift,
                              const int* __restrict__ ei) {
    int e = blockIdx.x * blockDim.x + threadIdx.x;
    if (e >= NE) return;
    int s = ei[e], d = ei[NE + e];
    float dx = pos[s * 3 + 0] - pos[d * 3 + 0] - shift[e * 3 + 0];
    float dy = pos[s * 3 + 1] - pos[d * 3 + 1] - shift[e * 3 + 1];
    float dz = pos[s * 3 + 2] - pos[d * 3 + 2] - shift[e * 3 + 2];
    g_w[e] = sqrtf(dx * dx + dy * dy + dz * dz);
}

// -------- h = emb[z] --------
__global__ void embed_kernel(const float* __restrict__ emb, const int* __restrict__ z) {
    int i = blockIdx.x * blockDim.x + threadIdx.x;
    if (i >= NN * H) return;
    int n = i >> 7, c = i & 127;
    g_h[i] = emb[z[n] * H + c];
}

__global__ void zero_misc_kernel() {
    int i = blockIdx.x * blockDim.x + threadIdx.x;
    if (i < NN) g_cnt[i] = 0;
    if (i < NGR) { g_gsum[i] = 0.0f; g_gcnt[i] = 0.0f; }
}

// -------- CSR build --------
__global__ void hist_kernel(const int* __restrict__ ei) {
    int e = blockIdx.x * blockDim.x + threadIdx.x;
    if (e >= NE) return;
    if (g_w[e] < WMAX) atomicAdd(&g_cnt[ei[NE + e]], 1);
}

__global__ void scan_kernel() {
    __shared__ int warp_sums[32];
    __shared__ int s_carry;
    int tid = threadIdx.x;
    int lane = tid & 31, wid = tid >> 5;
    if (tid == 0) { s_carry = 0; g_off[0] = 0; }
    __syncthreads();
    for (int base = 0; base < NN; base += 1024) {
        int i = base + tid;
        int v = (i < NN) ? g_cnt[i] : 0;
        int x = v;
#pragma unroll
        for (int o = 1; o < 32; o <<= 1) {
            int y = __shfl_up_sync(0xffffffffu, x, o);
            if (lane >= o) x += y;
        }
        if (lane == 31) warp_sums[wid] = x;
        __syncthreads();
        if (wid == 0) {
            int ws = warp_sums[lane];
#pragma unroll
            for (int o = 1; o < 32; o <<= 1) {
                int y = __shfl_up_sync(0xffffffffu, ws, o);
                if (lane >= o) ws += y;
            }
            warp_sums[lane] = ws;
        }
        __syncthreads();
        int incl = x + (wid > 0 ? warp_sums[wid - 1] : 0);
        int total = warp_sums[31];
        int carry = s_carry;
        if (i < NN) {
            g_off[i + 1] = carry + incl;
            g_cur[i] = carry + incl - v;
        }
        __syncthreads();
        if (tid == 0) s_carry = carry + total;
        __syncthreads();
    }
}

__global__ void fill_kernel(const int* __restrict__ ei) {
    int e = blockIdx.x * blockDim.x + threadIdx.x;
    if (e >= NE) return;
    float w = g_w[e];
    if (w >= WMAX) return;
    int d = ei[NE + e];
    int pos = atomicAdd(&g_cur[d], 1);
    float f = w * ((float)(TABN - 1) / WMAX);
    int i0 = (int)f;
    if (i0 > TABN - 2) i0 = TABN - 2;
    float fr = f - (float)i0;
    unsigned short hb = __half_as_ushort(__float2half_rn(fr));
    g_edges[pos] = make_uint2((unsigned)ei[e], ((unsigned)i0 << 16) | hb);
}

// -------- build Wf(w)*C(w) lookup table --------
__global__ void table_kernel(const float* __restrict__ w1, const float* __restrict__ b1,
                             const float* __restrict__ w2, const float* __restrict__ b2) {
    __shared__ float gs[8][NG];
    __shared__ float t1s[8][H];
    int s0 = blockIdx.x * 8;
    int j = threadIdx.x;
    const float step = WMAX / (float)(TABN - 1);
    const float spacing = 8.0f / 49.0f;
    const float coeff = -0.5f / (spacing * spacing);

    for (int idx = j; idx < 8 * NG; idx += blockDim.x) {
        int m = idx / NG, k = idx - m * NG;
        float ws = (float)(s0 + m) * step;
        float dd = ws - (float)k * spacing;
        gs[m][k] = expf(coeff * dd * dd);
    }
    __syncthreads();

    float acc[8];
#pragma unroll
    for (int m = 0; m < 8; m++) acc[m] = 0.0f;
    for (int k = 0; k < NG; k++) {
        float wv = w1[k * H + j];
#pragma unroll
        for (int m = 0; m < 8; m++) acc[m] += wv * gs[m][k];
    }
    float bb = b1[j];
#pragma unroll
    for (int m = 0; m < 8; m++) t1s[m][j] = ssp(acc[m] + bb);
    __syncthreads();

#pragma unroll
    for (int m = 0; m < 8; m++) acc[m] = 0.0f;
    for (int k = 0; k < H; k++) {
        float wv = w2[k * H + j];
#pragma unroll
        for (int m = 0; m < 8; m++) acc[m] += wv * t1s[m][k];
    }
    float b2v = b2[j];
#pragma unroll
    for (int m = 0; m < 8; m++) {
        float ws = (float)(s0 + m) * step;
        float C = 0.5f * (cosf(ws * (3.14159265358979f / 8.0f)) + 1.0f);
        g_tab[(s0 + m) * H + j] = (acc[m] + b2v) * C;
    }
}

// -------- delta table: tabd[i] = half(tab[i+H] - tab[i]) --------
__global__ void delta_kernel() {
    int i = blockIdx.x * blockDim.x + threadIdx.x;
    if (i >= (TABN - 1) * H) return;
    g_tabd[i] = __float2half_rn(g_tab[i + H] - g_tab[i]);
}

// -------- f32x2 packed GEMM: out = [ssp](in @ W + b) [+= residual] --------
// block 256, tile 64 rows x 128 cols. A resident in smem (32KB row-major),
// W staged as (k,k+1)-pairs (16KB). acc packs even/odd-k partial sums.
__global__ __launch_bounds__(256) void gemm128_kernel(
    const float* __restrict__ in, const float* __restrict__ W,
    const float* __restrict__ bias, float* __restrict__ out,
    int act, int residual) {
    __shared__ float As[GM * H];                        // 32 KB
    __shared__ unsigned long long WsP[(KC / 2) * H];    // 16 KB
    int n0 = blockIdx.x * GM;
    int tid = threadIdx.x;

    float4* As4 = (float4*)As;
    for (int i = tid; i < GM * H / 4; i += 256) {
        int m = i >> 5;
        float4 v = make_float4(0.f, 0.f, 0.f, 0.f);
        if (n0 + m < NN) v = ((const float4*)(in + (size_t)(n0 + m) * H))[i & 31];
        As4[i] = v;
    }

    int cx = tid & 31;
    int mg = tid >> 5;
    unsigned long long acc[8][4];
#pragma unroll
    for (int r = 0; r < 8; r++)
#pragma unroll
        for (int j = 0; j < 4; j++) acc[r][j] = 0ULL;

    for (int kc = 0; kc < H; kc += KC) {
        __syncthreads();
        for (int i = tid; i < (KC / 2) * H; i += 256) {
            int p = i >> 7, c = i & 127;
            int k = kc + 2 * p;
            float lo = W[(size_t)k * H + c];
            float hi = W[(size_t)(k + 1) * H + c];
            WsP[i] = (unsigned long long)__float_as_uint(lo)
                   | ((unsigned long long)__float_as_uint(hi) << 32);
        }
        __syncthreads();

#pragma unroll
        for (int k4 = 0; k4 < KC; k4 += 4) {
            int p = k4 >> 1;
            unsigned long long b01[4], b23[4];
#pragma unroll
            for (int j = 0; j < 4; j++) {
                int c = cx + 32 * j;
                b01[j] = WsP[p * H + c];
                b23[j] = WsP[(p + 1) * H + c];
            }
#pragma unroll
            for (int r = 0; r < 8; r++) {
                ulonglong2 a = *(const ulonglong2*)(As + (8 * mg + r) * H + kc + k4);
#pragma unroll
                for (int j = 0; j < 4; j++) {
                    fma2(acc[r][j], a.x, b01[j]);
                    fma2(acc[r][j], a.y, b23[j]);
                }
            }
        }
    }

#pragma unroll
    for (int r = 0; r < 8; r++) {
        int n = n0 + 8 * mg + r;
        if (n >= NN) break;
#pragma unroll
        for (int j = 0; j < 4; j++) {
            int c = cx + 32 * j;
            float lo = __uint_as_float((unsigned)(acc[r][j] & 0xffffffffULL));
            float hi = __uint_as_float((unsigned)(acc[r][j] >> 32));
            float v = lo + hi;
            if (bias) v += bias[c];
            if (act) v = ssp(v);
            float* op = out + (size_t)n * H + c;
            if (residual) v += *op;
            *op = v;
        }
    }
}

// -------- small GEMM for head (kin=128, kout=64) --------
__global__ void node_gemm_kernel(const float* __restrict__ in, const float* __restrict__ W,
                                 const float* __restrict__ bias, float* __restrict__ out,
                                 int kin, int kout, int act) {
    __shared__ float As[16 * H];
    int n0 = blockIdx.x * 16;
    for (int i = threadIdx.x; i < 16 * kin; i += blockDim.x)
        As[i] = in[n0 * kin + i];
    __syncthreads();
    int j = threadIdx.x;
    if (j < kout) {
        float acc[16];
#pragma unroll
        for (int m = 0; m < 16; m++) acc[m] = 0.0f;
        for (int k = 0; k < kin; k++) {
            float wv = W[k * kout + j];
#pragma unroll
            for (int m = 0; m < 16; m++) acc[m] += wv * As[m * kin + k];
        }
        float b = bias ? bias[j] : 0.0f;
#pragma unroll
        for (int m = 0; m < 16; m++) {
            float v = acc[m] + b;
            if (act) v = ssp(v);
            out[(n0 + m) * kout + j] = v;
        }
    }
}

// -------- gather: one warp per dst node, fp32 value + half delta lerp --------
__global__ __launch_bounds__(256) void gather_kernel() {
    int n = (blockIdx.x * blockDim.x + threadIdx.x) >> 5;
    int lane = threadIdx.x & 31;
    if (n >= NN) return;
    int p = g_off[n], end = g_off[n + 1];
    float4 acc = make_float4(0.f, 0.f, 0.f, 0.f);

    for (; p + 2 <= end; p += 2) {
        uint2 e0 = g_edges[p];
        uint2 e1 = g_edges[p + 1];
        int i00 = e0.y >> 16, i01 = e1.y >> 16;
        float fr0 = __half2float(__ushort_as_half((unsigned short)(e0.y & 0xffffu)));
        float fr1 = __half2float(__ushort_as_half((unsigned short)(e1.y & 0xffffu)));
        float4 a0 = ((const float4*)(g_tab + (size_t)i00 * H))[lane];
        uint2  d0 = ((const uint2*)(g_tabd + (size_t)i00 * H))[lane];
        float4 h0 = ((const float4*)(g_hx + (size_t)e0.x * H))[lane];
        float4 a1 = ((const float4*)(g_tab + (size_t)i01 * H))[lane];
        uint2  d1 = ((const uint2*)(g_tabd + (size_t)i01 * H))[lane];
        float4 h1 = ((const float4*)(g_hx + (size_t)e1.x * H))[lane];
        float2 d0lo = __half22float2(*(__half2*)&d0.x);
        float2 d0hi = __half22float2(*(__half2*)&d0.y);
        float2 d1lo = __half22float2(*(__half2*)&d1.x);
        float2 d1hi = __half22float2(*(__half2*)&d1.y);
        acc.x += h0.x * fmaf(fr0, d0lo.x, a0.x) + h1.x * fmaf(fr1, d1lo.x, a1.x);
        acc.y += h0.y * fmaf(fr0, d0lo.y, a0.y) + h1.y * fmaf(fr1, d1lo.y, a1.y);
        acc.z += h0.z * fmaf(fr0, d0hi.x, a0.z) + h1.z * fmaf(fr1, d1hi.x, a1.z);
        acc.w += h0.w * fmaf(fr0, d0hi.y, a0.w) + h1.w * fmaf(fr1, d1hi.y, a1.w);
    }
    if (p < end) {
        uint2 e0 = g_edges[p];
        int i00 = e0.y >> 16;
        float fr0 = __half2float(__ushort_as_half((unsigned short)(e0.y & 0xffffu)));
        float4 a0 = ((const float4*)(g_tab + (size_t)i00 * H))[lane];
        uint2  d0 = ((const uint2*)(g_tabd + (size_t)i00 * H))[lane];
        float4 h0 = ((const float4*)(g_hx + (size_t)e0.x * H))[lane];
        float2 d0lo = __half22float2(*(__half2*)&d0.x);
        float2 d0hi = __half22float2(*(__half2*)&d0.y);
        acc.x += h0.x * fmaf(fr0, d0lo.x, a0.x);
        acc.y += h0.y * fmaf(fr0, d0lo.y, a0.y);
        acc.z += h0.z * fmaf(fr0, d0hi.x, a0.z);
        acc.w += h0.w * fmaf(fr0, d0hi.y, a0.w);
    }
    ((float4*)(g_agg + (size_t)n * H))[lane] = acc;
}

// -------- head stage 2 + per-graph reduction --------
__global__ void head2_kernel(const float* __restrict__ w2, const float* __restrict__ b2,
                             const int* __restrict__ batch) {
    int n = (blockIdx.x * blockDim.x + threadIdx.x) >> 5;
    int lane = threadIdx.x & 31;
    if (n >= NN) return;
    float v = g_agg[n * 64 + lane] * w2[lane] + g_agg[n * 64 + 32 + lane] * w2[32 + lane];
#pragma unroll
    for (int o = 16; o > 0; o >>= 1) v += __shfl_down_sync(0xffffffffu, v, o);
    if (lane == 0) {
        int g = batch[n];
        atomicAdd(&g_gsum[g], v + b2[0]);
        atomicAdd(&g_gcnt[g], 1.0f);
    }
}

__global__ void finalize_kernel(float* __restrict__ out) {
    int g = threadIdx.x;
    if (g < NGR) out[g] = g_gsum[g] / fmaxf(g_gcnt[g], 1.0f);
}

extern "C" void kernel_launch(void* const* d_in, const int* in_sizes, int n_in,
                              void* d_out, int out_size) {
    const float* pos     = (const float*)d_in[0];
    const float* shift   = (const float*)d_in[1];
    const float* emb     = (const float*)d_in[2];
    const float* mlp_w1  = (const float*)d_in[3];
    const float* mlp_b1  = (const float*)d_in[4];
    const float* mlp_w2  = (const float*)d_in[5];
    const float* mlp_b2  = (const float*)d_in[6];
    const float* cf_w1   = (const float*)d_in[7];
    const float* cf_w2   = (const float*)d_in[8];
    const float* cf_b2   = (const float*)d_in[9];
    const float* lin_w   = (const float*)d_in[10];
    const float* lin_b   = (const float*)d_in[11];
    const float* head_w1 = (const float*)d_in[12];
    const float* head_b1 = (const float*)d_in[13];
    const float* head_w2 = (const float*)d_in[14];
    const float* head_b2 = (const float*)d_in[15];
    const int*   z       = (const int*)d_in[16];
    const int*   ei      = (const int*)d_in[17];
    const int*   batch   = (const int*)d_in[18];
    float* out = (float*)d_out;

    float *p_h, *p_hx, *p_agg;
    cudaGetSymbolAddress((void**)&p_h,   g_h);
    cudaGetSymbolAddress((void**)&p_hx,  g_hx);
    cudaGetSymbolAddress((void**)&p_agg, g_agg);

    const int gemm_blocks = (NN + GM - 1) / GM;

    edge_w_kernel<<<(NE + 255) / 256, 256>>>(pos, shift, ei);
    embed_kernel<<<(NN * H + 255) / 256, 256>>>(emb, z);
    zero_misc_kernel<<<(NN + 255) / 256, 256>>>();
    hist_kernel<<<(NE + 255) / 256, 256>>>(ei);
    scan_kernel<<<1, 1024>>>();
    fill_kernel<<<(NE + 255) / 256, 256>>>(ei);

    for (int i = 0; i < 3; i++) {
        table_kernel<<<TABN / 8, 128>>>(mlp_w1 + i * NG * H, mlp_b1 + i * H,
                                        mlp_w2 + i * H * H,  mlp_b2 + i * H);
        delta_kernel<<<((TABN - 1) * H + 255) / 256, 256>>>();
        // hx = h @ cf_w1[i]
        gemm128_kernel<<<gemm_blocks, 256>>>(p_h, cf_w1 + i * H * H, nullptr, p_hx, 0, 0);
        // agg[n] = sum_{e: dst=n} hx[src] * Wf(w)*C(w)
        gather_kernel<<<(NN * 32 + 255) / 256, 256>>>();
        // t = ssp(agg @ cf_w2 + b2)
        gemm128_kernel<<<gemm_blocks, 256>>>(p_agg, cf_w2 + i * H * H, cf_b2 + i * H, p_hx, 1, 0);
        // h += t @ lin_w + lin_b
        gemm128_kernel<<<gemm_blocks, 256>>>(p_hx, lin_w + i * H * H, lin_b + i * H, p_h, 0, 1);
    }

    node_gemm_kernel<<<(NN + 15) / 16, 128>>>(p_h, head_w1, head_b1, p_agg, H, 64, 1);
    head2_kernel<<<(NN * 32 + 255) / 256, 256>>>(head_w2, head_b2, batch);
    finalize_kernel<<<1, 128>>>(out);
}

// round 6
// speedup vs baseline: 1.1836x; 1.1836x over previous
#include <cuda_runtime.h>
#include <cuda_fp16.h>
#include <math.h>

#define NN 50000
#define NE 1600000
#define H 128
#define NG 50
#define NGR 128
#define TABN 8192
#define WMAX 9.6f
#define GM 64   // gemm M-tile
#define KC 32   // gemm K-chunk staged in smem

// -------- scratch (device globals: allocation-free) --------
__device__ float  g_h[NN * H];
__device__ float  g_hx[NN * H];
__device__ float  g_agg[NN * H];
__device__ float  g_w[NE];
__device__ float  g_tab[TABN * H];        // Wf(w)*C(w) values (fp32)
__device__ __half g_tabd[TABN * H];       // forward deltas (half)
__device__ float  g_gsum[NGR];
__device__ float  g_gcnt[NGR];
__device__ int    g_cnt[NN];
__device__ int    g_off[NN + 1];
__device__ int    g_cur[NN];
__device__ uint2  g_edges[NE];            // {src, (i0<<16)|half(fr)}

__device__ __forceinline__ float ssp(float x) {
    return fmaxf(x, 0.0f) + log1pf(expf(-fabsf(x))) - 0.69314718055994531f;
}

// -------- edge geometry --------
__global__ void edge_w_kernel(const float* __restrict__ pos,
                              const float* __restrict__ shift,
                              const int* __restrict__ ei) {
    int e = blockIdx.x * blockDim.x + threadIdx.x;
    if (e >= NE) return;
    int s = ei[e], d = ei[NE + e];
    float dx = pos[s * 3 + 0] - pos[d * 3 + 0] - shift[e * 3 + 0];
    float dy = pos[s * 3 + 1] - pos[d * 3 + 1] - shift[e * 3 + 1];
    float dz = pos[s * 3 + 2] - pos[d * 3 + 2] - shift[e * 3 + 2];
    g_w[e] = sqrtf(dx * dx + dy * dy + dz * dz);
}

// -------- h = emb[z] --------
__global__ void embed_kernel(const float* __restrict__ emb, const int* __restrict__ z) {
    int i = blockIdx.x * blockDim.x + threadIdx.x;
    if (i >= NN * H) return;
    int n = i >> 7, c = i & 127;
    g_h[i] = emb[z[n] * H + c];
}

__global__ void zero_misc_kernel() {
    int i = blockIdx.x * blockDim.x + threadIdx.x;
    if (i < NN) g_cnt[i] = 0;
    if (i < NGR) { g_gsum[i] = 0.0f; g_gcnt[i] = 0.0f; }
}

// -------- CSR build --------
__global__ void hist_kernel(const int* __restrict__ ei) {
    int e = blockIdx.x * blockDim.x + threadIdx.x;
    if (e >= NE) return;
    if (g_w[e] < WMAX) atomicAdd(&g_cnt[ei[NE + e]], 1);
}

__global__ void scan_kernel() {
    __shared__ int warp_sums[32];
    __shared__ int s_carry;
    int tid = threadIdx.x;
    int lane = tid & 31, wid = tid >> 5;
    if (tid == 0) { s_carry = 0; g_off[0] = 0; }
    __syncthreads();
    for (int base = 0; base < NN; base += 1024) {
        int i = base + tid;
        int v = (i < NN) ? g_cnt[i] : 0;
        int x = v;
#pragma unroll
        for (int o = 1; o < 32; o <<= 1) {
            int y = __shfl_up_sync(0xffffffffu, x, o);
            if (lane >= o) x += y;
        }
        if (lane == 31) warp_sums[wid] = x;
        __syncthreads();
        if (wid == 0) {
            int ws = warp_sums[lane];
#pragma unroll
            for (int o = 1; o < 32; o <<= 1) {
                int y = __shfl_up_sync(0xffffffffu, ws, o);
                if (lane >= o) ws += y;
            }
            warp_sums[lane] = ws;
        }
        __syncthreads();
        int incl = x + (wid > 0 ? warp_sums[wid - 1] : 0);
        int total = warp_sums[31];
        int carry = s_carry;
        if (i < NN) {
            g_off[i + 1] = carry + incl;
            g_cur[i] = carry + incl - v;
        }
        __syncthreads();
        if (tid == 0) s_carry = carry + total;
        __syncthreads();
    }
}

__global__ void fill_kernel(const int* __restrict__ ei) {
    int e = blockIdx.x * blockDim.x + threadIdx.x;
    if (e >= NE) return;
    float w = g_w[e];
    if (w >= WMAX) return;
    int d = ei[NE + e];
    int pos = atomicAdd(&g_cur[d], 1);
    float f = w * ((float)(TABN - 1) / WMAX);
    int i0 = (int)f;
    if (i0 > TABN - 2) i0 = TABN - 2;
    float fr = f - (float)i0;
    unsigned short hb = __half_as_ushort(__float2half_rn(fr));
    g_edges[pos] = make_uint2((unsigned)ei[e], ((unsigned)i0 << 16) | hb);
}

// -------- build Wf(w)*C(w) lookup table --------
__global__ void table_kernel(const float* __restrict__ w1, const float* __restrict__ b1,
                             const float* __restrict__ w2, const float* __restrict__ b2) {
    __shared__ float gs[8][NG];
    __shared__ float t1s[8][H];
    int s0 = blockIdx.x * 8;
    int j = threadIdx.x;
    const float step = WMAX / (float)(TABN - 1);
    const float spacing = 8.0f / 49.0f;
    const float coeff = -0.5f / (spacing * spacing);

    for (int idx = j; idx < 8 * NG; idx += blockDim.x) {
        int m = idx / NG, k = idx - m * NG;
        float ws = (float)(s0 + m) * step;
        float dd = ws - (float)k * spacing;
        gs[m][k] = expf(coeff * dd * dd);
    }
    __syncthreads();

    float acc[8];
#pragma unroll
    for (int m = 0; m < 8; m++) acc[m] = 0.0f;
    for (int k = 0; k < NG; k++) {
        float wv = w1[k * H + j];
#pragma unroll
        for (int m = 0; m < 8; m++) acc[m] += wv * gs[m][k];
    }
    float bb = b1[j];
#pragma unroll
    for (int m = 0; m < 8; m++) t1s[m][j] = ssp(acc[m] + bb);
    __syncthreads();

#pragma unroll
    for (int m = 0; m < 8; m++) acc[m] = 0.0f;
    for (int k = 0; k < H; k++) {
        float wv = w2[k * H + j];
#pragma unroll
        for (int m = 0; m < 8; m++) acc[m] += wv * t1s[m][k];
    }
    float b2v = b2[j];
#pragma unroll
    for (int m = 0; m < 8; m++) {
        float ws = (float)(s0 + m) * step;
        float C = 0.5f * (cosf(ws * (3.14159265358979f / 8.0f)) + 1.0f);
        g_tab[(s0 + m) * H + j] = (acc[m] + b2v) * C;
    }
}

// -------- delta table: tabd[i] = half(tab[i+H] - tab[i]) --------
__global__ void delta_kernel() {
    int i = blockIdx.x * blockDim.x + threadIdx.x;
    if (i >= (TABN - 1) * H) return;
    g_tabd[i] = __float2half_rn(g_tab[i + H] - g_tab[i]);
}

// -------- tiled node GEMM (round-4 proven float4 version) --------
// block 256 threads, tile 64 nodes x 128 cols. A resident in smem (32KB),
// W streamed through smem in 32-row chunks (16KB).
__global__ __launch_bounds__(256) void gemm128_kernel(
    const float* __restrict__ in, const float* __restrict__ W,
    const float* __restrict__ bias, float* __restrict__ out,
    int act, int residual) {
    __shared__ float As[GM * H];   // 32 KB
    __shared__ float Ws[KC * H];   // 16 KB
    int n0 = blockIdx.x * GM;
    int tid = threadIdx.x;

    float4* As4 = (float4*)As;
    for (int i = tid; i < GM * H / 4; i += 256) {
        int m = i >> 5;
        float4 v = make_float4(0.f, 0.f, 0.f, 0.f);
        if (n0 + m < NN) v = ((const float4*)(in + (size_t)(n0 + m) * H))[i & 31];
        As4[i] = v;
    }

    int cx = tid & 31;
    int mg = tid >> 5;
    float acc[8][4];
#pragma unroll
    for (int r = 0; r < 8; r++)
#pragma unroll
        for (int c = 0; c < 4; c++) acc[r][c] = 0.0f;

    for (int kc = 0; kc < H; kc += KC) {
        __syncthreads();
        const float4* Wc4 = (const float4*)(W + kc * H);
        float4* Ws4 = (float4*)Ws;
#pragma unroll
        for (int i = 0; i < KC * H / 4 / 256; i++)
            Ws4[tid + i * 256] = Wc4[tid + i * 256];
        __syncthreads();

#pragma unroll
        for (int k = 0; k < KC; k += 4) {
            float4 b0 = ((float4*)(Ws + (k + 0) * H))[cx];
            float4 b1 = ((float4*)(Ws + (k + 1) * H))[cx];
            float4 b2 = ((float4*)(Ws + (k + 2) * H))[cx];
            float4 b3 = ((float4*)(Ws + (k + 3) * H))[cx];
#pragma unroll
            for (int r = 0; r < 8; r++) {
                float4 av = *(float4*)(As + (8 * mg + r) * H + kc + k);
                acc[r][0] += av.x * b0.x + av.y * b1.x + av.z * b2.x + av.w * b3.x;
                acc[r][1] += av.x * b0.y + av.y * b1.y + av.z * b2.y + av.w * b3.y;
                acc[r][2] += av.x * b0.z + av.y * b1.z + av.z * b2.z + av.w * b3.z;
                acc[r][3] += av.x * b0.w + av.y * b1.w + av.z * b2.w + av.w * b3.w;
            }
        }
    }

    float4 bv = make_float4(0.f, 0.f, 0.f, 0.f);
    if (bias) bv = ((const float4*)bias)[cx];
#pragma unroll
    for (int r = 0; r < 8; r++) {
        int n = n0 + 8 * mg + r;
        if (n >= NN) break;
        float4 v;
        v.x = acc[r][0] + bv.x; v.y = acc[r][1] + bv.y;
        v.z = acc[r][2] + bv.z; v.w = acc[r][3] + bv.w;
        if (act) { v.x = ssp(v.x); v.y = ssp(v.y); v.z = ssp(v.z); v.w = ssp(v.w); }
        float4* op = (float4*)(out + (size_t)n * H) + cx;
        if (residual) {
            float4 o = *op;
            v.x += o.x; v.y += o.y; v.z += o.z; v.w += o.w;
        }
        *op = v;
    }
}

// -------- small GEMM for head (kin=128, kout=64) --------
__global__ void node_gemm_kernel(const float* __restrict__ in, const float* __restrict__ W,
                                 const float* __restrict__ bias, float* __restrict__ out,
                                 int kin, int kout, int act) {
    __shared__ float As[16 * H];
    int n0 = blockIdx.x * 16;
    for (int i = threadIdx.x; i < 16 * kin; i += blockDim.x)
        As[i] = in[n0 * kin + i];
    __syncthreads();
    int j = threadIdx.x;
    if (j < kout) {
        float acc[16];
#pragma unroll
        for (int m = 0; m < 16; m++) acc[m] = 0.0f;
        for (int k = 0; k < kin; k++) {
            float wv = W[k * kout + j];
#pragma unroll
            for (int m = 0; m < 16; m++) acc[m] += wv * As[m * kin + k];
        }
        float b = bias ? bias[j] : 0.0f;
#pragma unroll
        for (int m = 0; m < 16; m++) {
            float v = acc[m] + b;
            if (act) v = ssp(v);
            out[(n0 + m) * kout + j] = v;
        }
    }
}

// -------- gather: one warp per dst node, fp32 value + half delta lerp --------
__global__ __launch_bounds__(256) void gather_kernel() {
    int n = (blockIdx.x * blockDim.x + threadIdx.x) >> 5;
    int lane = threadIdx.x & 31;
    if (n >= NN) return;
    int p = g_off[n], end = g_off[n + 1];
    float4 acc = make_float4(0.f, 0.f, 0.f, 0.f);

    for (; p + 2 <= end; p += 2) {
        uint2 e0 = g_edges[p];
        uint2 e1 = g_edges[p + 1];
        int i00 = e0.y >> 16, i01 = e1.y >> 16;
        float fr0 = __half2float(__ushort_as_half((unsigned short)(e0.y & 0xffffu)));
        float fr1 = __half2float(__ushort_as_half((unsigned short)(e1.y & 0xffffu)));
        float4 a0 = ((const float4*)(g_tab + (size_t)i00 * H))[lane];
        uint2  d0 = ((const uint2*)(g_tabd + (size_t)i00 * H))[lane];
        float4 h0 = ((const float4*)(g_hx + (size_t)e0.x * H))[lane];
        float4 a1 = ((const float4*)(g_tab + (size_t)i01 * H))[lane];
        uint2  d1 = ((const uint2*)(g_tabd + (size_t)i01 * H))[lane];
        float4 h1 = ((const float4*)(g_hx + (size_t)e1.x * H))[lane];
        float2 d0lo = __half22float2(*(__half2*)&d0.x);
        float2 d0hi = __half22float2(*(__half2*)&d0.y);
        float2 d1lo = __half22float2(*(__half2*)&d1.x);
        float2 d1hi = __half22float2(*(__half2*)&d1.y);
        acc.x += h0.x * fmaf(fr0, d0lo.x, a0.x) + h1.x * fmaf(fr1, d1lo.x, a1.x);
        acc.y += h0.y * fmaf(fr0, d0lo.y, a0.y) + h1.y * fmaf(fr1, d1lo.y, a1.y);
        acc.z += h0.z * fmaf(fr0, d0hi.x, a0.z) + h1.z * fmaf(fr1, d1hi.x, a1.z);
        acc.w += h0.w * fmaf(fr0, d0hi.y, a0.w) + h1.w * fmaf(fr1, d1hi.y, a1.w);
    }
    if (p < end) {
        uint2 e0 = g_edges[p];
        int i00 = e0.y >> 16;
        float fr0 = __half2float(__ushort_as_half((unsigned short)(e0.y & 0xffffu)));
        float4 a0 = ((const float4*)(g_tab + (size_t)i00 * H))[lane];
        uint2  d0 = ((const uint2*)(g_tabd + (size_t)i00 * H))[lane];
        float4 h0 = ((const float4*)(g_hx + (size_t)e0.x * H))[lane];
        float2 d0lo = __half22float2(*(__half2*)&d0.x);
        float2 d0hi = __half22float2(*(__half2*)&d0.y);
        acc.x += h0.x * fmaf(fr0, d0lo.x, a0.x);
        acc.y += h0.y * fmaf(fr0, d0lo.y, a0.y);
        acc.z += h0.z * fmaf(fr0, d0hi.x, a0.z);
        acc.w += h0.w * fmaf(fr0, d0hi.y, a0.w);
    }
    ((float4*)(g_agg + (size_t)n * H))[lane] = acc;
}

// -------- head stage 2 + per-graph reduction --------
__global__ void head2_kernel(const float* __restrict__ w2, const float* __restrict__ b2,
                             const int* __restrict__ batch) {
    int n = (blockIdx.x * blockDim.x + threadIdx.x) >> 5;
    int lane = threadIdx.x & 31;
    if (n >= NN) return;
    float v = g_agg[n * 64 + lane] * w2[lane] + g_agg[n * 64 + 32 + lane] * w2[32 + lane];
#pragma unroll
    for (int o = 16; o > 0; o >>= 1) v += __shfl_down_sync(0xffffffffu, v, o);
    if (lane == 0) {
        int g = batch[n];
        atomicAdd(&g_gsum[g], v + b2[0]);
        atomicAdd(&g_gcnt[g], 1.0f);
    }
}

__global__ void finalize_kernel(float* __restrict__ out) {
    int g = threadIdx.x;
    if (g < NGR) out[g] = g_gsum[g] / fmaxf(g_gcnt[g], 1.0f);
}

extern "C" void kernel_launch(void* const* d_in, const int* in_sizes, int n_in,
                              void* d_out, int out_size) {
    const float* pos     = (const float*)d_in[0];
    const float* shift   = (const float*)d_in[1];
    const float* emb     = (const float*)d_in[2];
    const float* mlp_w1  = (const float*)d_in[3];
    const float* mlp_b1  = (const float*)d_in[4];
    const float* mlp_w2  = (const float*)d_in[5];
    const float* mlp_b2  = (const float*)d_in[6];
    const float* cf_w1   = (const float*)d_in[7];
    const float* cf_w2   = (const float*)d_in[8];
    const float* cf_b2   = (const float*)d_in[9];
    const float* lin_w   = (const float*)d_in[10];
    const float* lin_b   = (const float*)d_in[11];
    const float* head_w1 = (const float*)d_in[12];
    const float* head_b1 = (const float*)d_in[13];
    const float* head_w2 = (const float*)d_in[14];
    const float* head_b2 = (const float*)d_in[15];
    const int*   z       = (const int*)d_in[16];
    const int*   ei      = (const int*)d_in[17];
    const int*   batch   = (const int*)d_in[18];
    float* out = (float*)d_out;

    float *p_h, *p_hx, *p_agg;
    cudaGetSymbolAddress((void**)&p_h,   g_h);
    cudaGetSymbolAddress((void**)&p_hx,  g_hx);
    cudaGetSymbolAddress((void**)&p_agg, g_agg);

    const int gemm_blocks = (NN + GM - 1) / GM;

    edge_w_kernel<<<(NE + 255) / 256, 256>>>(pos, shift, ei);
    embed_kernel<<<(NN * H + 255) / 256, 256>>>(emb, z);
    zero_misc_kernel<<<(NN + 255) / 256, 256>>>();
    hist_kernel<<<(NE + 255) / 256, 256>>>(ei);
    scan_kernel<<<1, 1024>>>();
    fill_kernel<<<(NE + 255) / 256, 256>>>(ei);

    for (int i = 0; i < 3; i++) {
        table_kernel<<<TABN / 8, 128>>>(mlp_w1 + i * NG * H, mlp_b1 + i * H,
                                        mlp_w2 + i * H * H,  mlp_b2 + i * H);
        delta_kernel<<<((TABN - 1) * H + 255) / 256, 256>>>();
        // hx = h @ cf_w1[i]
        gemm128_kernel<<<gemm_blocks, 256>>>(p_h, cf_w1 + i * H * H, nullptr, p_hx, 0, 0);
        // agg[n] = sum_{e: dst=n} hx[src] * Wf(w)*C(w)
        gather_kernel<<<(NN * 32 + 255) / 256, 256>>>();
        // t = ssp(agg @ cf_w2 + b2)
        gemm128_kernel<<<gemm_blocks, 256>>>(p_agg, cf_w2 + i * H * H, cf_b2 + i * H, p_hx, 1, 0);
        // h += t @ lin_w + lin_b
        gemm128_kernel<<<gemm_blocks, 256>>>(p_hx, lin_w + i * H * H, lin_b + i * H, p_h, 0, 1);
    }

    node_gemm_kernel<<<(NN + 15) / 16, 128>>>(p_h, head_w1, head_b1, p_agg, H, 64, 1);
    head2_kernel<<<(NN * 32 + 255) / 256, 256>>>(head_w2, head_b2, batch);
    finalize_kernel<<<1, 128>>>(out);
}

// round 7
// speedup vs baseline: 1.2742x; 1.0766x over previous
#include <cuda_runtime.h>
#include <cuda_fp16.h>
#include <cuda_bf16.h>
#include <math.h>

#define NN 50000
#define NE 1600000
#define H 128
#define NG 50
#define NGR 128
#define TABN 8192
#define WMAX 9.6f

// -------- scratch (device globals: allocation-free) --------
__device__ float  g_h[NN * H];
__device__ float  g_hx[NN * H];
__device__ float  g_agg[NN * H];
__device__ float  g_w[NE];
__device__ float  g_tab[TABN * H];        // Wf(w)*C(w) values (fp32)
__device__ __half g_tabd[TABN * H];       // forward deltas (half)
__device__ float  g_gsum[NGR];
__device__ float  g_gcnt[NGR];
__device__ int    g_cnt[NN];
__device__ int    g_off[NN + 1];
__device__ int    g_cur[NN];
__device__ uint2  g_edges[NE];            // {src, (i0<<16)|half(fr)}

__device__ __forceinline__ float ssp(float x) {
    return fmaxf(x, 0.0f) + log1pf(expf(-fabsf(x))) - 0.69314718055994531f;
}

__device__ __forceinline__ unsigned sptr(const void* p) {
    return (unsigned)__cvta_generic_to_shared(p);
}

__device__ __forceinline__ void ldsm4(unsigned d[4], unsigned addr) {
    asm volatile("ldmatrix.sync.aligned.m8n8.x4.shared.b16 {%0,%1,%2,%3}, [%4];"
                 : "=r"(d[0]), "=r"(d[1]), "=r"(d[2]), "=r"(d[3]) : "r"(addr));
}

__device__ __forceinline__ void ldsm4t(unsigned d[4], unsigned addr) {
    asm volatile("ldmatrix.sync.aligned.m8n8.x4.trans.shared.b16 {%0,%1,%2,%3}, [%4];"
                 : "=r"(d[0]), "=r"(d[1]), "=r"(d[2]), "=r"(d[3]) : "r"(addr));
}

__device__ __forceinline__ void mma16816(float c[4], const unsigned a[4],
                                         unsigned b0, unsigned b1) {
    asm volatile("mma.sync.aligned.m16n8k16.row.col.f32.bf16.bf16.f32 "
                 "{%0,%1,%2,%3}, {%4,%5,%6,%7}, {%8,%9}, {%0,%1,%2,%3};"
                 : "+f"(c[0]), "+f"(c[1]), "+f"(c[2]), "+f"(c[3])
                 : "r"(a[0]), "r"(a[1]), "r"(a[2]), "r"(a[3]), "r"(b0), "r"(b1));
}

__device__ __forceinline__ unsigned packbf(float x, float y) {
    __nv_bfloat162 t = __floats2bfloat162_rn(x, y);
    return *(unsigned*)&t;
}

// -------- edge geometry --------
__global__ void edge_w_kernel(const float* __restrict__ pos,
                              const float* __restrict__ shift,
                              const int* __restrict__ ei) {
    int e = blockIdx.x * blockDim.x + threadIdx.x;
    if (e >= NE) return;
    int s = ei[e], d = ei[NE + e];
    float dx = pos[s * 3 + 0] - pos[d * 3 + 0] - shift[e * 3 + 0];
    float dy = pos[s * 3 + 1] - pos[d * 3 + 1] - shift[e * 3 + 1];
    float dz = pos[s * 3 + 2] - pos[d * 3 + 2] - shift[e * 3 + 2];
    g_w[e] = sqrtf(dx * dx + dy * dy + dz * dz);
}

// -------- h = emb[z] --------
__global__ void embed_kernel(const float* __restrict__ emb, const int* __restrict__ z) {
    int i = blockIdx.x * blockDim.x + threadIdx.x;
    if (i >= NN * H) return;
    int n = i >> 7, c = i & 127;
    g_h[i] = emb[z[n] * H + c];
}

__global__ void zero_misc_kernel() {
    int i = blockIdx.x * blockDim.x + threadIdx.x;
    if (i < NN) g_cnt[i] = 0;
    if (i < NGR) { g_gsum[i] = 0.0f; g_gcnt[i] = 0.0f; }
}

// -------- CSR build --------
__global__ void hist_kernel(const int* __restrict__ ei) {
    int e = blockIdx.x * blockDim.x + threadIdx.x;
    if (e >= NE) return;
    if (g_w[e] < WMAX) atomicAdd(&g_cnt[ei[NE + e]], 1);
}

__global__ void scan_kernel() {
    __shared__ int warp_sums[32];
    __shared__ int s_carry;
    int tid = threadIdx.x;
    int lane = tid & 31, wid = tid >> 5;
    if (tid == 0) { s_carry = 0; g_off[0] = 0; }
    __syncthreads();
    for (int base = 0; base < NN; base += 1024) {
        int i = base + tid;
        int v = (i < NN) ? g_cnt[i] : 0;
        int x = v;
#pragma unroll
        for (int o = 1; o < 32; o <<= 1) {
            int y = __shfl_up_sync(0xffffffffu, x, o);
            if (lane >= o) x += y;
        }
        if (lane == 31) warp_sums[wid] = x;
        __syncthreads();
        if (wid == 0) {
            int ws = warp_sums[lane];
#pragma unroll
            for (int o = 1; o < 32; o <<= 1) {
                int y = __shfl_up_sync(0xffffffffu, ws, o);
                if (lane >= o) ws += y;
            }
            warp_sums[lane] = ws;
        }
        __syncthreads();
        int incl = x + (wid > 0 ? warp_sums[wid - 1] : 0);
        int total = warp_sums[31];
        int carry = s_carry;
        if (i < NN) {
            g_off[i + 1] = carry + incl;
            g_cur[i] = carry + incl - v;
        }
        __syncthreads();
        if (tid == 0) s_carry = carry + total;
        __syncthreads();
    }
}

__global__ void fill_kernel(const int* __restrict__ ei) {
    int e = blockIdx.x * blockDim.x + threadIdx.x;
    if (e >= NE) return;
    float w = g_w[e];
    if (w >= WMAX) return;
    int d = ei[NE + e];
    int pos = atomicAdd(&g_cur[d], 1);
    float f = w * ((float)(TABN - 1) / WMAX);
    int i0 = (int)f;
    if (i0 > TABN - 2) i0 = TABN - 2;
    float fr = f - (float)i0;
    unsigned short hb = __half_as_ushort(__float2half_rn(fr));
    g_edges[pos] = make_uint2((unsigned)ei[e], ((unsigned)i0 << 16) | hb);
}

// -------- build Wf(w)*C(w) lookup table --------
__global__ void table_kernel(const float* __restrict__ w1, const float* __restrict__ b1,
                             const float* __restrict__ w2, const float* __restrict__ b2) {
    __shared__ float gs[8][NG];
    __shared__ float t1s[8][H];
    int s0 = blockIdx.x * 8;
    int j = threadIdx.x;
    const float step = WMAX / (float)(TABN - 1);
    const float spacing = 8.0f / 49.0f;
    const float coeff = -0.5f / (spacing * spacing);

    for (int idx = j; idx < 8 * NG; idx += blockDim.x) {
        int m = idx / NG, k = idx - m * NG;
        float ws = (float)(s0 + m) * step;
        float dd = ws - (float)k * spacing;
        gs[m][k] = expf(coeff * dd * dd);
    }
    __syncthreads();

    float acc[8];
#pragma unroll
    for (int m = 0; m < 8; m++) acc[m] = 0.0f;
    for (int k = 0; k < NG; k++) {
        float wv = w1[k * H + j];
#pragma unroll
        for (int m = 0; m < 8; m++) acc[m] += wv * gs[m][k];
    }
    float bb = b1[j];
#pragma unroll
    for (int m = 0; m < 8; m++) t1s[m][j] = ssp(acc[m] + bb);
    __syncthreads();

#pragma unroll
    for (int m = 0; m < 8; m++) acc[m] = 0.0f;
    for (int k = 0; k < H; k++) {
        float wv = w2[k * H + j];
#pragma unroll
        for (int m = 0; m < 8; m++) acc[m] += wv * t1s[m][k];
    }
    float b2v = b2[j];
#pragma unroll
    for (int m = 0; m < 8; m++) {
        float ws = (float)(s0 + m) * step;
        float C = 0.5f * (cosf(ws * (3.14159265358979f / 8.0f)) + 1.0f);
        g_tab[(s0 + m) * H + j] = (acc[m] + b2v) * C;
    }
}

// -------- delta table: tabd[i] = half(tab[i+H] - tab[i]) --------
__global__ void delta_kernel() {
    int i = blockIdx.x * blockDim.x + threadIdx.x;
    if (i >= (TABN - 1) * H) return;
    g_tabd[i] = __float2half_rn(g_tab[i + H] - g_tab[i]);
}

// -------- tensor-core node GEMM: out = [ssp](in @ W + b) [+= residual] --------
// bf16 2-term split (hi+lo): D = Ahi*Whi + Ahi*Wlo + Alo*Whi, fp32 accum.
// block 256 (8 warps), tile 128 rows x 128 cols, K streamed in 32-chunks.
__global__ __launch_bounds__(256) void gemm_mma_kernel(
    const float* __restrict__ in, const float* __restrict__ W,
    const float* __restrict__ bias, float* __restrict__ out,
    int act, int residual) {
    __shared__ __nv_bfloat16 sAhi[128][40];   // 10240 B
    __shared__ __nv_bfloat16 sAlo[128][40];   // 10240 B
    __shared__ __nv_bfloat16 sWhi[32][136];   // 8704 B
    __shared__ __nv_bfloat16 sWlo[32][136];   // 8704 B

    int tid = threadIdx.x;
    int wid = tid >> 5, lane = tid & 31;
    int n0 = blockIdx.x * 128;

    float acc[16][4];
#pragma unroll
    for (int t = 0; t < 16; t++)
#pragma unroll
        for (int j = 0; j < 4; j++) acc[t][j] = 0.0f;

    for (int kc = 0; kc < H; kc += 32) {
        __syncthreads();
        // stage A chunk [128 rows x 32 cols] as hi/lo bf16
        for (int i = tid; i < 1024; i += 256) {
            int m = i >> 3;         // row within tile
            int c4 = i & 7;         // float4 index (8 per row)
            float4 v = make_float4(0.f, 0.f, 0.f, 0.f);
            if (n0 + m < NN)
                v = *(const float4*)(in + (size_t)(n0 + m) * H + kc + c4 * 4);
            __nv_bfloat16 h0 = __float2bfloat16(v.x), h1 = __float2bfloat16(v.y);
            __nv_bfloat16 h2 = __float2bfloat16(v.z), h3 = __float2bfloat16(v.w);
            float l0 = v.x - __bfloat162float(h0), l1 = v.y - __bfloat162float(h1);
            float l2 = v.z - __bfloat162float(h2), l3 = v.w - __bfloat162float(h3);
            uint2 hp, lp;
            hp.x = packbf(__bfloat162float(h0), __bfloat162float(h1));
            hp.y = packbf(__bfloat162float(h2), __bfloat162float(h3));
            lp.x = packbf(l0, l1);
            lp.y = packbf(l2, l3);
            *(uint2*)&sAhi[m][c4 * 4] = hp;
            *(uint2*)&sAlo[m][c4 * 4] = lp;
        }
        // stage W chunk [32 rows x 128 cols] as hi/lo bf16
        for (int i = tid; i < 1024; i += 256) {
            int r = i >> 5;         // k-row within chunk
            int c4 = i & 31;        // float4 index (32 per row)
            float4 v = *(const float4*)(W + (size_t)(kc + r) * H + c4 * 4);
            __nv_bfloat16 h0 = __float2bfloat16(v.x), h1 = __float2bfloat16(v.y);
            __nv_bfloat16 h2 = __float2bfloat16(v.z), h3 = __float2bfloat16(v.w);
            float l0 = v.x - __bfloat162float(h0), l1 = v.y - __bfloat162float(h1);
            float l2 = v.z - __bfloat162float(h2), l3 = v.w - __bfloat162float(h3);
            uint2 hp, lp;
            hp.x = packbf(__bfloat162float(h0), __bfloat162float(h1));
            hp.y = packbf(__bfloat162float(h2), __bfloat162float(h3));
            lp.x = packbf(l0, l1);
            lp.y = packbf(l2, l3);
            *(uint2*)&sWhi[r][c4 * 4] = hp;
            *(uint2*)&sWlo[r][c4 * 4] = lp;
        }
        __syncthreads();

#pragma unroll
        for (int kk = 0; kk < 32; kk += 16) {
            unsigned ahi[4], alo[4];
            unsigned arow = wid * 16 + (lane & 15);
            unsigned acol = kk + (lane >> 4) * 8;
            ldsm4(ahi, sptr(&sAhi[arow][acol]));
            ldsm4(alo, sptr(&sAlo[arow][acol]));
#pragma unroll
            for (int np = 0; np < 8; np++) {
                unsigned bhi[4], blo[4];
                unsigned brow = kk + (lane & 15);
                unsigned bcol = np * 16 + (lane >> 4) * 8;
                ldsm4t(bhi, sptr(&sWhi[brow][bcol]));
                ldsm4t(blo, sptr(&sWlo[brow][bcol]));
                mma16816(acc[2 * np],     ahi, bhi[0], bhi[1]);
                mma16816(acc[2 * np + 1], ahi, bhi[2], bhi[3]);
                mma16816(acc[2 * np],     ahi, blo[0], blo[1]);
                mma16816(acc[2 * np + 1], ahi, blo[2], blo[3]);
                mma16816(acc[2 * np],     alo, bhi[0], bhi[1]);
                mma16816(acc[2 * np + 1], alo, bhi[2], bhi[3]);
            }
        }
    }

    // epilogue: thread holds (r0,c),(r0,c+1),(r1,c),(r1,c+1) per n-tile
    int r0 = n0 + wid * 16 + (lane >> 2);
    int r1 = r0 + 8;
    int cbase = (lane & 3) * 2;
#pragma unroll
    for (int nt = 0; nt < 16; nt++) {
        int c = nt * 8 + cbase;
        float bx = bias ? bias[c] : 0.0f;
        float by = bias ? bias[c + 1] : 0.0f;
        if (r0 < NN) {
            float x = acc[nt][0] + bx, y = acc[nt][1] + by;
            if (act) { x = ssp(x); y = ssp(y); }
            float2* op = (float2*)(out + (size_t)r0 * H + c);
            if (residual) { float2 o = *op; x += o.x; y += o.y; }
            *op = make_float2(x, y);
        }
        if (r1 < NN) {
            float x = acc[nt][2] + bx, y = acc[nt][3] + by;
            if (act) { x = ssp(x); y = ssp(y); }
            float2* op = (float2*)(out + (size_t)r1 * H + c);
            if (residual) { float2 o = *op; x += o.x; y += o.y; }
            *op = make_float2(x, y);
        }
    }
}

// -------- small GEMM for head (kin=128, kout=64) --------
__global__ void node_gemm_kernel(const float* __restrict__ in, const float* __restrict__ W,
                                 const float* __restrict__ bias, float* __restrict__ out,
                                 int kin, int kout, int act) {
    __shared__ float As[16 * H];
    int n0 = blockIdx.x * 16;
    for (int i = threadIdx.x; i < 16 * kin; i += blockDim.x)
        As[i] = in[n0 * kin + i];
    __syncthreads();
    int j = threadIdx.x;
    if (j < kout) {
        float acc[16];
#pragma unroll
        for (int m = 0; m < 16; m++) acc[m] = 0.0f;
        for (int k = 0; k < kin; k++) {
            float wv = W[k * kout + j];
#pragma unroll
            for (int m = 0; m < 16; m++) acc[m] += wv * As[m * kin + k];
        }
        float b = bias ? bias[j] : 0.0f;
#pragma unroll
        for (int m = 0; m < 16; m++) {
            float v = acc[m] + b;
            if (act) v = ssp(v);
            out[(n0 + m) * kout + j] = v;
        }
    }
}

// -------- gather: one warp per dst node, fp32 value + half delta lerp --------
__global__ __launch_bounds__(256) void gather_kernel() {
    int n = (blockIdx.x * blockDim.x + threadIdx.x) >> 5;
    int lane = threadIdx.x & 31;
    if (n >= NN) return;
    int p = g_off[n], end = g_off[n + 1];
    float4 acc = make_float4(0.f, 0.f, 0.f, 0.f);

    for (; p + 2 <= end; p += 2) {
        uint2 e0 = g_edges[p];
        uint2 e1 = g_edges[p + 1];
        int i00 = e0.y >> 16, i01 = e1.y >> 16;
        float fr0 = __half2float(__ushort_as_half((unsigned short)(e0.y & 0xffffu)));
        float fr1 = __half2float(__ushort_as_half((unsigned short)(e1.y & 0xffffu)));
        float4 a0 = ((const float4*)(g_tab + (size_t)i00 * H))[lane];
        uint2  d0 = ((const uint2*)(g_tabd + (size_t)i00 * H))[lane];
        float4 h0 = ((const float4*)(g_hx + (size_t)e0.x * H))[lane];
        float4 a1 = ((const float4*)(g_tab + (size_t)i01 * H))[lane];
        uint2  d1 = ((const uint2*)(g_tabd + (size_t)i01 * H))[lane];
        float4 h1 = ((const float4*)(g_hx + (size_t)e1.x * H))[lane];
        float2 d0lo = __half22float2(*(__half2*)&d0.x);
        float2 d0hi = __half22float2(*(__half2*)&d0.y);
        float2 d1lo = __half22float2(*(__half2*)&d1.x);
        float2 d1hi = __half22float2(*(__half2*)&d1.y);
        acc.x += h0.x * fmaf(fr0, d0lo.x, a0.x) + h1.x * fmaf(fr1, d1lo.x, a1.x);
        acc.y += h0.y * fmaf(fr0, d0lo.y, a0.y) + h1.y * fmaf(fr1, d1lo.y, a1.y);
        acc.z += h0.z * fmaf(fr0, d0hi.x, a0.z) + h1.z * fmaf(fr1, d1hi.x, a1.z);
        acc.w += h0.w * fmaf(fr0, d0hi.y, a0.w) + h1.w * fmaf(fr1, d1hi.y, a1.w);
    }
    if (p < end) {
        uint2 e0 = g_edges[p];
        int i00 = e0.y >> 16;
        float fr0 = __half2float(__ushort_as_half((unsigned short)(e0.y & 0xffffu)));
        float4 a0 = ((const float4*)(g_tab + (size_t)i00 * H))[lane];
        uint2  d0 = ((const uint2*)(g_tabd + (size_t)i00 * H))[lane];
        float4 h0 = ((const float4*)(g_hx + (size_t)e0.x * H))[lane];
        float2 d0lo = __half22float2(*(__half2*)&d0.x);
        float2 d0hi = __half22float2(*(__half2*)&d0.y);
        acc.x += h0.x * fmaf(fr0, d0lo.x, a0.x);
        acc.y += h0.y * fmaf(fr0, d0lo.y, a0.y);
        acc.z += h0.z * fmaf(fr0, d0hi.x, a0.z);
        acc.w += h0.w * fmaf(fr0, d0hi.y, a0.w);
    }
    ((float4*)(g_agg + (size_t)n * H))[lane] = acc;
}

// -------- head stage 2 + per-graph reduction --------
__global__ void head2_kernel(const float* __restrict__ w2, const float* __restrict__ b2,
                             const int* __restrict__ batch) {
    int n = (blockIdx.x * blockDim.x + threadIdx.x) >> 5;
    int lane = threadIdx.x & 31;
    if (n >= NN) return;
    float v = g_agg[n * 64 + lane] * w2[lane] + g_agg[n * 64 + 32 + lane] * w2[32 + lane];
#pragma unroll
    for (int o = 16; o > 0; o >>= 1) v += __shfl_down_sync(0xffffffffu, v, o);
    if (lane == 0) {
        int g = batch[n];
        atomicAdd(&g_gsum[g], v + b2[0]);
        atomicAdd(&g_gcnt[g], 1.0f);
    }
}

__global__ void finalize_kernel(float* __restrict__ out) {
    int g = threadIdx.x;
    if (g < NGR) out[g] = g_gsum[g] / fmaxf(g_gcnt[g], 1.0f);
}

extern "C" void kernel_launch(void* const* d_in, const int* in_sizes, int n_in,
                              void* d_out, int out_size) {
    const float* pos     = (const float*)d_in[0];
    const float* shift   = (const float*)d_in[1];
    const float* emb     = (const float*)d_in[2];
    const float* mlp_w1  = (const float*)d_in[3];
    const float* mlp_b1  = (const float*)d_in[4];
    const float* mlp_w2  = (const float*)d_in[5];
    const float* mlp_b2  = (const float*)d_in[6];
    const float* cf_w1   = (const float*)d_in[7];
    const float* cf_w2   = (const float*)d_in[8];
    const float* cf_b2   = (const float*)d_in[9];
    const float* lin_w   = (const float*)d_in[10];
    const float* lin_b   = (const float*)d_in[11];
    const float* head_w1 = (const float*)d_in[12];
    const float* head_b1 = (const float*)d_in[13];
    const float* head_w2 = (const float*)d_in[14];
    const float* head_b2 = (const float*)d_in[15];
    const int*   z       = (const int*)d_in[16];
    const int*   ei      = (const int*)d_in[17];
    const int*   batch   = (const int*)d_in[18];
    float* out = (float*)d_out;

    float *p_h, *p_hx, *p_agg;
    cudaGetSymbolAddress((void**)&p_h,   g_h);
    cudaGetSymbolAddress((void**)&p_hx,  g_hx);
    cudaGetSymbolAddress((void**)&p_agg, g_agg);

    const int mma_blocks = (NN + 127) / 128;

    edge_w_kernel<<<(NE + 255) / 256, 256>>>(pos, shift, ei);
    embed_kernel<<<(NN * H + 255) / 256, 256>>>(emb, z);
    zero_misc_kernel<<<(NN + 255) / 256, 256>>>();
    hist_kernel<<<(NE + 255) / 256, 256>>>(ei);
    scan_kernel<<<1, 1024>>>();
    fill_kernel<<<(NE + 255) / 256, 256>>>(ei);

    for (int i = 0; i < 3; i++) {
        table_kernel<<<TABN / 8, 128>>>(mlp_w1 + i * NG * H, mlp_b1 + i * H,
                                        mlp_w2 + i * H * H,  mlp_b2 + i * H);
        delta_kernel<<<((TABN - 1) * H + 255) / 256, 256>>>();
        // hx = h @ cf_w1[i]
        gemm_mma_kernel<<<mma_blocks, 256>>>(p_h, cf_w1 + i * H * H, nullptr, p_hx, 0, 0);
        // agg[n] = sum_{e: dst=n} hx[src] * Wf(w)*C(w)
        gather_kernel<<<(NN * 32 + 255) / 256, 256>>>();
        // t = ssp(agg @ cf_w2 + b2)
        gemm_mma_kernel<<<mma_blocks, 256>>>(p_agg, cf_w2 + i * H * H, cf_b2 + i * H, p_hx, 1, 0);
        // h += t @ lin_w + lin_b
        gemm_mma_kernel<<<mma_blocks, 256>>>(p_hx, lin_w + i * H * H, lin_b + i * H, p_h, 0, 1);
    }

    node_gemm_kernel<<<(NN + 15) / 16, 128>>>(p_h, head_w1, head_b1, p_agg, H, 64, 1);
    head2_kernel<<<(NN * 32 + 255) / 256, 256>>>(head_w2, head_b2, batch);
    finalize_kernel<<<1, 128>>>(out);
}